// round 8
// baseline (speedup 1.0000x reference)
#include <cuda_runtime.h>
#include <cuda_bf16.h>
#include <math.h>
#include <stdint.h>

// ---------------------------------------------------------------------------
// WanS2VTransformerBlock — round 8:
//  * GEMM warp geometry 2x2 (4 warps, 64x64 warp tile) — smem reads 48->32KB
//    per chunk; 128 threads, 2 CTAs/SM
//  * register-resident softmax (1 read + 1 bf16 write)
//  * sigmoid-form fast GELU (__expf), __expf softmax
// ---------------------------------------------------------------------------

namespace {
constexpr int Dm   = 1536;
constexpr int Hn   = 12;
constexpr int DHd  = 128;
constexpr int FFNd = 8960;
constexpr int Bb   = 2;
constexpr int Ss   = 2048;
constexpr int Le   = 512;
constexpr int NTOK = Bb * Ss;          // 4096
constexpr int NENC = Bb * Le;          // 1024
}

// ---- fp32 scratch ---------------------------------------------------------
__device__ float g_q[NTOK * Dm];
__device__ float g_k[NTOK * Dm];
__device__ float g_v[NTOK * Dm];
__device__ float g_t[NTOK * Dm];
__device__ float g_h[NTOK * Dm];
__device__ float g_s[Bb * Hn * Ss * Ss];

// ---- bf16 hi/lo activation scratch ---------------------------------------
__device__ __nv_bfloat16 g_xhi[NTOK * Dm], g_xlo[NTOK * Dm];
__device__ __nv_bfloat16 g_hhi[NTOK * Dm], g_hlo[NTOK * Dm];
__device__ __nv_bfloat16 g_ehi[NENC * Dm], g_elo[NENC * Dm];
__device__ __nv_bfloat16 g_fhi[NTOK * FFNd], g_flo[NTOK * FFNd];
__device__ __nv_bfloat16 g_qhi[NTOK * Dm], g_qlo[NTOK * Dm];
__device__ __nv_bfloat16 g_khi[NTOK * Dm], g_klo[NTOK * Dm];
__device__ __nv_bfloat16 g_vthi[NTOK * Dm], g_vtlo[NTOK * Dm];
__device__ __nv_bfloat16 g_phi[Bb * Hn * Ss * Ss], g_plo[Bb * Hn * Ss * Ss];

// ---- bf16 hi/lo transposed weights ([N][K] row-major, K contiguous) -------
__device__ __nv_bfloat16 g_wsq_hi[8 * Dm * Dm], g_wsq_lo[8 * Dm * Dm];
__device__ __nv_bfloat16 g_wf1_hi[FFNd * Dm],  g_wf1_lo[FFNd * Dm];
__device__ __nv_bfloat16 g_wf2_hi[Dm * FFNd],  g_wf2_lo[Dm * FFNd];

__device__ __forceinline__ void* dev_buf(int id) {
    switch (id) {
        case 0:  return (void*)g_q;
        case 1:  return (void*)g_k;
        case 2:  return (void*)g_v;
        case 4:  return (void*)g_t;
        case 5:  return (void*)g_h;
        case 6:  return (void*)g_s;
        case 7:  return (void*)g_xhi;
        case 8:  return (void*)g_xlo;
        case 9:  return (void*)g_hhi;
        case 10: return (void*)g_hlo;
        case 11: return (void*)g_ehi;
        case 12: return (void*)g_elo;
        case 13: return (void*)g_fhi;
        case 14: return (void*)g_flo;
        case 15: return (void*)g_wsq_hi;
        case 16: return (void*)g_wsq_lo;
        case 17: return (void*)g_wf1_hi;
        case 18: return (void*)g_wf1_lo;
        case 19: return (void*)g_wf2_hi;
        case 20: return (void*)g_wf2_lo;
        case 21: return (void*)g_qhi;
        case 22: return (void*)g_qlo;
        case 23: return (void*)g_khi;
        case 24: return (void*)g_klo;
        case 25: return (void*)g_vthi;
        case 26: return (void*)g_vtlo;
        case 27: return (void*)g_phi;
        case 28: return (void*)g_plo;
    }
    return nullptr;
}

__device__ __forceinline__ uint32_t smem_to_u32(const void* p) {
    uint32_t a;
    asm("{ .reg .u64 t; cvta.to.shared.u64 t, %1; cvt.u32.u64 %0, t; }"
        : "=r"(a) : "l"(p));
    return a;
}

// ---- mma.sync / ldmatrix / cp.async helpers (sm_80+) ----------------------
__device__ __forceinline__ void ldsm_x4(uint32_t* r, uint32_t addr) {
    asm volatile("ldmatrix.sync.aligned.m8n8.x4.shared.b16 {%0,%1,%2,%3}, [%4];"
        : "=r"(r[0]), "=r"(r[1]), "=r"(r[2]), "=r"(r[3]) : "r"(addr));
}
__device__ __forceinline__ void ldsm_x2(uint32_t* r, uint32_t addr) {
    asm volatile("ldmatrix.sync.aligned.m8n8.x2.shared.b16 {%0,%1}, [%2];"
        : "=r"(r[0]), "=r"(r[1]) : "r"(addr));
}
__device__ __forceinline__ void mma_bf16(float* c, const uint32_t* a, const uint32_t* b) {
    asm volatile(
        "mma.sync.aligned.m16n8k16.row.col.f32.bf16.bf16.f32 "
        "{%0,%1,%2,%3}, {%4,%5,%6,%7}, {%8,%9}, {%0,%1,%2,%3};"
        : "+f"(c[0]), "+f"(c[1]), "+f"(c[2]), "+f"(c[3])
        : "r"(a[0]), "r"(a[1]), "r"(a[2]), "r"(a[3]), "r"(b[0]), "r"(b[1]));
}
__device__ __forceinline__ void cp16(uint32_t s, const void* g) {
    asm volatile("cp.async.cg.shared.global [%0], [%1], 16;" :: "r"(s), "l"(g));
}
#define CP_COMMIT() asm volatile("cp.async.commit_group;" ::: "memory")
#define CP_WAIT0()  asm volatile("cp.async.wait_group 0;"  ::: "memory")

__device__ __forceinline__ float gelu_fast(float x) {
    float z = 1.5957691216057308f * (x + 0.044715f * x * x * x);
    return x / (1.0f + __expf(-z));
}

// ===========================================================================
// bf16 3-pass GEMM: C[M,N] = A[M,K] * B[N,K]^T  (+scale, +bias, +gelu)
// Block tile 128x128, 4 warps (2x2), warp tile 64x64, K-chunk 16,
// 2-stage cp.async, static 48KB smem.
// ===========================================================================
namespace {
constexpr int KC  = 16;
constexpr int RS  = 24;                 // row stride (elems); 48B conflict-free
constexpr int TSE = 128 * RS;           // 3072 elems per tile
}

__global__ __launch_bounds__(128, 2) void gemm_mma_k(
    int ahiId, int aloId, int lda, long long aOffB, long long aOffH,
    int bhiId, int bloId, int ldb, long long bOff0, long long bOffB, long long bOffH,
    float* cfExt, int cfId, int chiId, int cloId, int ldc, long long cOffB, long long cOffH,
    const float* __restrict__ bias, int K, int act, float cscale)
{
    __shared__ __align__(16) __nv_bfloat16 smem[2 * 4 * TSE];   // 49152 B

    const int z = blockIdx.z;
    const int bz = z / Hn;
    const int hz = z - bz * Hn;

    const __nv_bfloat16* Ahi = (const __nv_bfloat16*)dev_buf(ahiId) + bz * aOffB + hz * aOffH;
    const __nv_bfloat16* Alo = (const __nv_bfloat16*)dev_buf(aloId) + bz * aOffB + hz * aOffH;
    const __nv_bfloat16* Bhi = (const __nv_bfloat16*)dev_buf(bhiId) + bOff0 + bz * bOffB + hz * bOffH;
    const __nv_bfloat16* Blo = (const __nv_bfloat16*)dev_buf(bloId) + bOff0 + bz * bOffB + hz * bOffH;
    long long cOff = bz * cOffB + hz * cOffH;
    float* Cf = cfExt ? cfExt : (cfId >= 0 ? (float*)dev_buf(cfId) : nullptr);
    if (Cf) Cf += cOff;
    __nv_bfloat16* Chi = (chiId >= 0) ? (__nv_bfloat16*)dev_buf(chiId) + cOff : nullptr;
    __nv_bfloat16* Clo = (cloId >= 0) ? (__nv_bfloat16*)dev_buf(cloId) + cOff : nullptr;

    const int tid  = threadIdx.x;
    const int wid  = tid >> 5;
    const int lane = tid & 31;
    const int wm   = (wid & 1) * 64;       // 2 row bands
    const int wn   = (wid >> 1) * 64;      // 2 col bands
    const int row0 = blockIdx.y * 128;
    const int col0 = blockIdx.x * 128;

    const uint32_t sbase = smem_to_u32(smem);
    // loader: 128 threads, each thread covers row=tid, cols {0,8} per tile
    const int lrow = tid;

    const int a_r = lane & 15;
    const int a_c = (lane >> 4) * 8;
    const int b_r = lane & 7;
    const int b_c = ((lane >> 3) & 1) * 8;

    float acc[4][8][4];
#pragma unroll
    for (int i = 0; i < 4; i++)
#pragma unroll
        for (int j = 0; j < 8; j++)
#pragma unroll
            for (int r = 0; r < 4; r++) acc[i][j][r] = 0.0f;

    const int NC = K / KC;

    auto load_chunk = [&](int stg, int k0) {
        uint32_t sb = sbase + (uint32_t)(stg * 4 * TSE) * 2;
        size_t ga = (size_t)(row0 + lrow) * lda + k0;
        size_t gb = (size_t)(col0 + lrow) * ldb + k0;
        uint32_t so = (uint32_t)(lrow * RS) * 2;
#pragma unroll
        for (int cc = 0; cc < 2; cc++) {
            uint32_t soc = so + cc * 16;
            int gc = cc * 8;
            cp16(sb + soc,                          Ahi + ga + gc);
            cp16(sb + (uint32_t)TSE * 2     + soc,  Alo + ga + gc);
            cp16(sb + (uint32_t)TSE * 2 * 2 + soc,  Bhi + gb + gc);
            cp16(sb + (uint32_t)TSE * 2 * 3 + soc,  Blo + gb + gc);
        }
        CP_COMMIT();
    };

    load_chunk(0, 0);

    for (int c = 0; c < NC; c++) {
        CP_WAIT0();
        __syncthreads();
        if (c + 1 < NC) load_chunk((c + 1) & 1, (c + 1) * KC);

        const uint32_t sb = sbase + (uint32_t)((c & 1) * 4 * TSE) * 2;
        const uint32_t aHiB = sb;
        const uint32_t aLoB = sb + (uint32_t)TSE * 2;
        const uint32_t bHiB = sb + (uint32_t)TSE * 2 * 2;
        const uint32_t bLoB = sb + (uint32_t)TSE * 2 * 3;

        uint32_t bh[8][2], bl[8][2];
#pragma unroll
        for (int j = 0; j < 8; j++) {
            uint32_t ad = (uint32_t)(((wn + j * 8 + b_r) * RS + b_c) * 2);
            ldsm_x2(bh[j], bHiB + ad);
            ldsm_x2(bl[j], bLoB + ad);
        }
#pragma unroll
        for (int i = 0; i < 4; i++) {
            uint32_t ad = (uint32_t)(((wm + i * 16 + a_r) * RS + a_c) * 2);
            uint32_t ah[4], al[4];
            ldsm_x4(ah, aHiB + ad);
            ldsm_x4(al, aLoB + ad);
#pragma unroll
            for (int j = 0; j < 8; j++) {
                mma_bf16(acc[i][j], ah, bh[j]);
                mma_bf16(acc[i][j], ah, bl[j]);
                mma_bf16(acc[i][j], al, bh[j]);
            }
        }
        __syncthreads();
    }

    // ---- epilogue ----
    const int er = lane >> 2;
    const int ec = (lane & 3) * 2;
#pragma unroll
    for (int i = 0; i < 4; i++) {
#pragma unroll
        for (int rr = 0; rr < 2; rr++) {
            size_t m = (size_t)(row0 + wm + i * 16 + er + rr * 8);
#pragma unroll
            for (int j = 0; j < 8; j++) {
                int n = col0 + wn + j * 8 + ec;
                float v0 = acc[i][j][rr * 2 + 0] * cscale;
                float v1 = acc[i][j][rr * 2 + 1] * cscale;
                if (bias) { v0 += bias[n]; v1 += bias[n + 1]; }
                if (act == 1) { v0 = gelu_fast(v0); v1 = gelu_fast(v1); }
                if (Cf) {
                    float2 o; o.x = v0; o.y = v1;
                    *(float2*)&Cf[m * (size_t)ldc + n] = o;
                }
                if (Chi) {
                    __nv_bfloat16 h0 = __float2bfloat16(v0);
                    __nv_bfloat16 h1 = __float2bfloat16(v1);
                    __nv_bfloat16 l0 = __float2bfloat16(v0 - __bfloat162float(h0));
                    __nv_bfloat16 l1 = __float2bfloat16(v1 - __bfloat162float(h1));
                    __nv_bfloat162 ph; ph.x = h0; ph.y = h1;
                    __nv_bfloat162 pl; pl.x = l0; pl.y = l1;
                    *(__nv_bfloat162*)&Chi[m * (size_t)ldc + n] = ph;
                    *(__nv_bfloat162*)&Clo[m * (size_t)ldc + n] = pl;
                }
            }
        }
    }
}

// ===========================================================================
// Weight transpose + hi/lo conversion: W[K,N] -> T[N,K]
// ===========================================================================
__global__ __launch_bounds__(256) void transp_conv_k(
    const float* __restrict__ W, int thiId, int tloId, long long off, int K, int N)
{
    __nv_bfloat16* Thi = (__nv_bfloat16*)dev_buf(thiId) + off;
    __nv_bfloat16* Tlo = (__nv_bfloat16*)dev_buf(tloId) + off;
    __shared__ float tile[32][33];
    int nx = blockIdx.x * 32, ky = blockIdx.y * 32;
    int tx = threadIdx.x, ty = threadIdx.y;
#pragma unroll
    for (int j = 0; j < 32; j += 8)
        tile[ty + j][tx] = W[(size_t)(ky + ty + j) * N + nx + tx];
    __syncthreads();
#pragma unroll
    for (int j = 0; j < 32; j += 8) {
        float v = tile[tx][ty + j];
        size_t o = (size_t)(nx + ty + j) * K + ky + tx;
        __nv_bfloat16 hi = __float2bfloat16(v);
        Thi[o] = hi;
        Tlo[o] = __float2bfloat16(v - __bfloat162float(hi));
    }
}

// fp32 -> bf16 hi/lo
__global__ __launch_bounds__(256) void conv_k(
    const float* srcExt, int srcId, int hiId, int loId, int n)
{
    const float* src = srcExt ? srcExt : (const float*)dev_buf(srcId);
    __nv_bfloat16* hi = (__nv_bfloat16*)dev_buf(hiId);
    __nv_bfloat16* lo = (__nv_bfloat16*)dev_buf(loId);
    int i = blockIdx.x * 256 + threadIdx.x;
    if (i >= n) return;
    float v = src[i];
    __nv_bfloat16 h = __float2bfloat16(v);
    hi[i] = h;
    lo[i] = __float2bfloat16(v - __bfloat162float(h));
}

// ===========================================================================
// LayerNorm + AdaLN modulation -> bf16 hi/lo
// ===========================================================================
__global__ __launch_bounds__(256) void ln_mod_k(
    int dhiId, int dloId, const float* srcExt, int srcId,
    const float* __restrict__ temb, const float* __restrict__ sst,
    const int* __restrict__ segp, int jshift, int jscale)
{
    __nv_bfloat16* dhi = (__nv_bfloat16*)dev_buf(dhiId);
    __nv_bfloat16* dlo = (__nv_bfloat16*)dev_buf(dloId);
    const float* src = srcExt ? srcExt : (const float*)dev_buf(srcId);
    int tok = blockIdx.x;
    int b = tok / Ss;
    int s = tok - b * Ss;
    int si = segp[0];
    si = si < 0 ? 0 : (si > Ss ? Ss : si);
    int seg = (s >= si) ? 1 : 0;

    const float* x = src + (size_t)tok * Dm;
    int tid = threadIdx.x;
    float lsum = 0.0f, lsq = 0.0f;
    for (int d = tid; d < Dm; d += 256) {
        float v = x[d];
        lsum += v; lsq += v * v;
    }
    __shared__ float r1[256], r2[256];
    r1[tid] = lsum; r2[tid] = lsq;
    __syncthreads();
    for (int o = 128; o > 0; o >>= 1) {
        if (tid < o) { r1[tid] += r1[tid + o]; r2[tid] += r2[tid + o]; }
        __syncthreads();
    }
    float mu = r1[0] * (1.0f / Dm);
    float var = r2[0] * (1.0f / Dm) - mu * mu;
    float rstd = rsqrtf(var + 1e-6f);

    const float* tb_sc = temb + ((size_t)(b * 6 + jscale) * 2 + seg) * Dm;
    const float* tb_sh = temb + ((size_t)(b * 6 + jshift) * 2 + seg) * Dm;
    size_t base = (size_t)tok * Dm;
    for (int d = tid; d < Dm; d += 256) {
        float sc = sst[jscale * Dm + d] + tb_sc[d];
        float sh = sst[jshift * Dm + d] + tb_sh[d];
        float v = (x[d] - mu) * rstd * (1.0f + sc) + sh;
        __nv_bfloat16 h = __float2bfloat16(v);
        dhi[base + d] = h;
        dlo[base + d] = __float2bfloat16(v - __bfloat162float(h));
    }
}

// ===========================================================================
// RoPE: read g_q/g_k fp32, rotate, emit hi/lo bf16
// ===========================================================================
__global__ __launch_bounds__(256) void rope_split_k(const float* cs, const float* sn)
{
    int idx = blockIdx.x * 256 + threadIdx.x;
    const int total = NTOK * Hn * (DHd / 2);
    if (idx >= total) return;
    int i = idx & 63;
    int h = (idx >> 6) % Hn;
    int tok = idx / (64 * Hn);
    float c = cs[(size_t)tok * 64 + i];
    float sv = sn[(size_t)tok * 64 + i];
    size_t base = (size_t)tok * Dm + h * DHd + 2 * i;

    float xr = g_q[base], xi = g_q[base + 1];
    float o0 = xr * c - xi * sv;
    float o1 = xr * sv + xi * c;
    __nv_bfloat16 h0 = __float2bfloat16(o0);
    __nv_bfloat16 h1 = __float2bfloat16(o1);
    g_qhi[base] = h0; g_qhi[base + 1] = h1;
    g_qlo[base]     = __float2bfloat16(o0 - __bfloat162float(h0));
    g_qlo[base + 1] = __float2bfloat16(o1 - __bfloat162float(h1));

    xr = g_k[base]; xi = g_k[base + 1];
    o0 = xr * c - xi * sv;
    o1 = xr * sv + xi * c;
    h0 = __float2bfloat16(o0);
    h1 = __float2bfloat16(o1);
    g_khi[base] = h0; g_khi[base + 1] = h1;
    g_klo[base]     = __float2bfloat16(o0 - __bfloat162float(h0));
    g_klo[base + 1] = __float2bfloat16(o1 - __bfloat162float(h1));
}

// ===========================================================================
// V transpose per head: g_v [b*Lkv+n][h*128+d] -> vt[z][d][n] (hi/lo bf16)
// ===========================================================================
__global__ void vt_k(int Lkv)
{
    __shared__ float t[32][33];
    int z = blockIdx.z, b = z / Hn, h = z - b * Hn;
    int n0 = blockIdx.x * 32, d0 = blockIdx.y * 32;
    int tx = threadIdx.x, ty = threadIdx.y;
#pragma unroll
    for (int j = 0; j < 32; j += 8)
        t[ty + j][tx] = g_v[(size_t)(b * Lkv + n0 + ty + j) * Dm + h * DHd + d0 + tx];
    __syncthreads();
    size_t zb = (size_t)z * DHd * Lkv;
#pragma unroll
    for (int j = 0; j < 32; j += 8) {
        float v = t[tx][ty + j];
        size_t o = zb + (size_t)(d0 + ty + j) * Lkv + n0 + tx;
        __nv_bfloat16 hi = __float2bfloat16(v);
        g_vthi[o] = hi;
        g_vtlo[o] = __float2bfloat16(v - __bfloat162float(hi));
    }
}

// ===========================================================================
// Register-resident softmax -> P bf16 hi/lo. One 256-thread block per row.
// Lkv/256 <= 8 elements live in registers; single gmem read + bf16 write.
// ===========================================================================
__global__ __launch_bounds__(256) void softmax_bf_k(int Lkv)
{
    long long base = (long long)blockIdx.x * Lkv;
    const float* p = g_s + base;
    int tid = threadIdx.x;
    int ne = Lkv >> 8;              // 8 (self) or 2 (cross)
    float vals[8];
    __shared__ float red[256];

    float m = -1e30f;
    for (int e = 0; e < ne; e++) {
        vals[e] = p[e * 256 + tid];
        m = fmaxf(m, vals[e]);
    }
    red[tid] = m;
    __syncthreads();
    for (int o = 128; o > 0; o >>= 1) {
        if (tid < o) red[tid] = fmaxf(red[tid], red[tid + o]);
        __syncthreads();
    }
    float mx = red[0];
    __syncthreads();

    float s = 0.0f;
    for (int e = 0; e < ne; e++) {
        float ev = __expf(vals[e] - mx);
        vals[e] = ev;
        s += ev;
    }
    red[tid] = s;
    __syncthreads();
    for (int o = 128; o > 0; o >>= 1) {
        if (tid < o) red[tid] += red[tid + o];
        __syncthreads();
    }
    float inv = 1.0f / red[0];
    for (int e = 0; e < ne; e++) {
        float ev = vals[e] * inv;
        __nv_bfloat16 h = __float2bfloat16(ev);
        g_phi[base + e * 256 + tid] = h;
        g_plo[base + e * 256 + tid] = __float2bfloat16(ev - __bfloat162float(h));
    }
}

// ===========================================================================
// Gated residual: dst = hsrc + g_t*mod[j]; optional bf16 hi/lo duplicate
// ===========================================================================
__global__ __launch_bounds__(256) void resid_gate_k(
    float* dstExt, int dstId, int dhiId, int dloId,
    const float* hExt, int hId,
    const float* __restrict__ temb, const float* __restrict__ sst,
    const int* __restrict__ segp, int j)
{
    float* dst = dstExt ? dstExt : (float*)dev_buf(dstId);
    const float* h = hExt ? hExt : (const float*)dev_buf(hId);
    __nv_bfloat16* dhi = (dhiId >= 0) ? (__nv_bfloat16*)dev_buf(dhiId) : nullptr;
    __nv_bfloat16* dlo = (dloId >= 0) ? (__nv_bfloat16*)dev_buf(dloId) : nullptr;
    int idx = blockIdx.x * 256 + threadIdx.x;
    int d = idx % Dm;
    int tok = idx / Dm;
    int b = tok / Ss;
    int s = tok - b * Ss;
    int si = segp[0];
    si = si < 0 ? 0 : (si > Ss ? Ss : si);
    int seg = (s >= si) ? 1 : 0;
    float g = sst[j * Dm + d] + temb[((size_t)(b * 6 + j) * 2 + seg) * Dm + d];
    float v = h[idx] + g_t[idx] * g;
    dst[idx] = v;
    if (dhi) {
        __nv_bfloat16 hh = __float2bfloat16(v);
        dhi[idx] = hh;
        dlo[idx] = __float2bfloat16(v - __bfloat162float(hh));
    }
}

__global__ __launch_bounds__(256) void resid_add_k()
{
    int idx = blockIdx.x * 256 + threadIdx.x;
    g_h[idx] += g_t[idx];
}

// ===========================================================================
extern "C" void kernel_launch(void* const* d_in, const int* in_sizes, int n_in,
                              void* d_out, int out_size)
{
    const float* hidden = (const float*)d_in[0];
    const float* enc    = (const float*)d_in[1];
    const float* temb   = (const float*)d_in[2];
    const float* rc     = (const float*)d_in[3];
    const float* rs     = (const float*)d_in[4];
    const int*   seg    = (const int*)d_in[5];
    const float* Wq1 = (const float*)d_in[6];
    const float* Wk1 = (const float*)d_in[7];
    const float* Wv1 = (const float*)d_in[8];
    const float* Wo1 = (const float*)d_in[9];
    const float* bo1 = (const float*)d_in[10];
    const float* Wq2 = (const float*)d_in[11];
    const float* Wk2 = (const float*)d_in[12];
    const float* Wv2 = (const float*)d_in[13];
    const float* Wo2 = (const float*)d_in[14];
    const float* bo2 = (const float*)d_in[15];
    const float* Wf1 = (const float*)d_in[16];
    const float* bf1 = (const float*)d_in[17];
    const float* Wf2 = (const float*)d_in[18];
    const float* bf2 = (const float*)d_in[19];
    const float* sst = (const float*)d_in[20];
    float* out = (float*)d_out;

    const float scale = 0.08838834764831845f;  // 1/sqrt(128)
    const long long DD = (long long)Dm * Dm;
    const int nElem = NTOK * Dm;

    // ---- 0. weight transposes + hi/lo conversions --------------------------
    {
        dim3 tb(32, 8);
        dim3 gs(Dm / 32, Dm / 32);
        transp_conv_k<<<gs, tb>>>(Wq1, 15, 16, 0 * DD, Dm, Dm);
        transp_conv_k<<<gs, tb>>>(Wk1, 15, 16, 1 * DD, Dm, Dm);
        transp_conv_k<<<gs, tb>>>(Wv1, 15, 16, 2 * DD, Dm, Dm);
        transp_conv_k<<<gs, tb>>>(Wo1, 15, 16, 3 * DD, Dm, Dm);
        transp_conv_k<<<gs, tb>>>(Wq2, 15, 16, 4 * DD, Dm, Dm);
        transp_conv_k<<<gs, tb>>>(Wk2, 15, 16, 5 * DD, Dm, Dm);
        transp_conv_k<<<gs, tb>>>(Wv2, 15, 16, 6 * DD, Dm, Dm);
        transp_conv_k<<<gs, tb>>>(Wo2, 15, 16, 7 * DD, Dm, Dm);
        transp_conv_k<<<dim3(FFNd / 32, Dm / 32), tb>>>(Wf1, 17, 18, 0, Dm, FFNd);
        transp_conv_k<<<dim3(Dm / 32, FFNd / 32), tb>>>(Wf2, 19, 20, 0, FFNd, Dm);
    }

    dim3 gproj(Dm / 128, NTOK / 128);   // (12, 32)

    // ---- 1. LN + modulation -> x(hi/lo) ------------------------------------
    ln_mod_k<<<NTOK, 256>>>(7, 8, hidden, -1, temb, sst, seg, 0, 1);

    // ---- 2. QKV projections --------------------------------------------------
    gemm_mma_k<<<gproj, 128>>>(7, 8, Dm, 0, 0, 15, 16, Dm, 0 * DD, 0, 0,
                               nullptr, 0, -1, -1, Dm, 0, 0, nullptr, Dm, 0, 1.0f);
    gemm_mma_k<<<gproj, 128>>>(7, 8, Dm, 0, 0, 15, 16, Dm, 1 * DD, 0, 0,
                               nullptr, 1, -1, -1, Dm, 0, 0, nullptr, Dm, 0, 1.0f);
    gemm_mma_k<<<gproj, 128>>>(7, 8, Dm, 0, 0, 15, 16, Dm, 2 * DD, 0, 0,
                               nullptr, 2, -1, -1, Dm, 0, 0, nullptr, Dm, 0, 1.0f);

    // ---- 3. RoPE -> q/k hi/lo; V transpose -> vt hi/lo ---------------------
    rope_split_k<<<(NTOK * Hn * 64) / 256, 256>>>(rc, rs);
    vt_k<<<dim3(Ss / 32, DHd / 32, Bb * Hn), dim3(32, 8)>>>(Ss);

    // ---- 4. self QK^T (scaled) -> g_s --------------------------------------
    gemm_mma_k<<<dim3(Ss / 128, Ss / 128, Bb * Hn), 128>>>(
        21, 22, Dm, (long long)Ss * Dm, DHd,
        23, 24, Dm, 0, (long long)Ss * Dm, DHd,
        nullptr, 6, -1, -1, Ss, (long long)Hn * Ss * Ss, (long long)Ss * Ss,
        nullptr, DHd, 0, scale);

    // ---- 5. softmax -> P hi/lo ---------------------------------------------
    softmax_bf_k<<<Bb * Hn * Ss, 256>>>(Ss);

    // ---- 6. PV -> attention out hi/lo (merged layout) ----------------------
    gemm_mma_k<<<dim3(1, Ss / 128, Bb * Hn), 128>>>(
        27, 28, Ss, (long long)Hn * Ss * Ss, (long long)Ss * Ss,
        25, 26, Ss, 0, (long long)Hn * DHd * Ss, (long long)DHd * Ss,
        nullptr, -1, 7, 8, Dm, (long long)Ss * Dm, DHd,
        nullptr, Ss, 0, 1.0f);

    // ---- 7. out projection 1 (+bias) -> g_t --------------------------------
    gemm_mma_k<<<gproj, 128>>>(7, 8, Dm, 0, 0, 15, 16, Dm, 3 * DD, 0, 0,
                               nullptr, 4, -1, -1, Dm, 0, 0, bo1, Dm, 0, 1.0f);

    // ---- 8. gated residual -> g_h (+hi/lo) ---------------------------------
    resid_gate_k<<<nElem / 256, 256>>>(nullptr, 5, 9, 10, hidden, -1,
                                       temb, sst, seg, 2);

    // ---- 9. cross projections ----------------------------------------------
    gemm_mma_k<<<gproj, 128>>>(9, 10, Dm, 0, 0, 15, 16, Dm, 4 * DD, 0, 0,
                               nullptr, -1, 21, 22, Dm, 0, 0, nullptr, Dm, 0, 1.0f);
    conv_k<<<(NENC * Dm) / 256, 256>>>(enc, -1, 11, 12, NENC * Dm);
    dim3 gkv(Dm / 128, NENC / 128);   // (12, 8)
    gemm_mma_k<<<gkv, 128>>>(11, 12, Dm, 0, 0, 15, 16, Dm, 5 * DD, 0, 0,
                             nullptr, -1, 23, 24, Dm, 0, 0, nullptr, Dm, 0, 1.0f);
    gemm_mma_k<<<gkv, 128>>>(11, 12, Dm, 0, 0, 15, 16, Dm, 6 * DD, 0, 0,
                             nullptr, 2, -1, -1, Dm, 0, 0, nullptr, Dm, 0, 1.0f);
    vt_k<<<dim3(Le / 32, DHd / 32, Bb * Hn), dim3(32, 8)>>>(Le);

    // ---- 10. cross attention ------------------------------------------------
    gemm_mma_k<<<dim3(Le / 128, Ss / 128, Bb * Hn), 128>>>(
        21, 22, Dm, (long long)Ss * Dm, DHd,
        23, 24, Dm, 0, (long long)Le * Dm, DHd,
        nullptr, 6, -1, -1, Le, (long long)Hn * Ss * Le, (long long)Ss * Le,
        nullptr, DHd, 0, scale);
    softmax_bf_k<<<Bb * Hn * Ss, 256>>>(Le);
    gemm_mma_k<<<dim3(1, Ss / 128, Bb * Hn), 128>>>(
        27, 28, Le, (long long)Hn * Ss * Le, (long long)Ss * Le,
        25, 26, Le, 0, (long long)Hn * DHd * Le, (long long)DHd * Le,
        nullptr, -1, 7, 8, Dm, (long long)Ss * Dm, DHd,
        nullptr, Le, 0, 1.0f);

    // ---- 11. out projection 2 (+bias) + residual ---------------------------
    gemm_mma_k<<<gproj, 128>>>(7, 8, Dm, 0, 0, 15, 16, Dm, 7 * DD, 0, 0,
                               nullptr, 4, -1, -1, Dm, 0, 0, bo2, Dm, 0, 1.0f);
    resid_add_k<<<nElem / 256, 256>>>();

    // ---- 12. LN + c_shift/c_scale -> x(hi/lo) ------------------------------
    ln_mod_k<<<NTOK, 256>>>(7, 8, nullptr, 5, temb, sst, seg, 3, 4);

    // ---- 13. FFN up (+bias +gelu) -> f(hi/lo) ------------------------------
    gemm_mma_k<<<dim3(FFNd / 128, NTOK / 128), 128>>>(
        7, 8, Dm, 0, 0, 17, 18, Dm, 0, 0, 0,
        nullptr, -1, 13, 14, FFNd, 0, 0, bf1, Dm, 1, 1.0f);

    // ---- 14. FFN down (+bias) ----------------------------------------------
    gemm_mma_k<<<gproj, 128>>>(13, 14, FFNd, 0, 0, 19, 20, FFNd, 0, 0, 0,
                               nullptr, 4, -1, -1, Dm, 0, 0, bf2, FFNd, 0, 1.0f);

    // ---- 15. final gated residual -> d_out ---------------------------------
    resid_gate_k<<<nElem / 256, 256>>>(out, -1, -1, -1, nullptr, 5,
                                       temb, sst, seg, 5);
}

// round 9
// speedup vs baseline: 1.1936x; 1.1936x over previous
#include <cuda_runtime.h>
#include <cuda_bf16.h>
#include <math.h>
#include <stdint.h>

// ---------------------------------------------------------------------------
// WanS2VTransformerBlock — round 9:
//  * GEMM geometry reverted to R7 (256 thr, 2x4 warps, 64x32 tiles) — the
//    R8 2x2/128-thr variant dropped to 8 warps/SM and was issue-bound
//  * keep register softmax + fast GELU from R8
//  * B fragments via ldmatrix.x4 pairs (LDSM/chunk 16 -> 12)
// ---------------------------------------------------------------------------

namespace {
constexpr int Dm   = 1536;
constexpr int Hn   = 12;
constexpr int DHd  = 128;
constexpr int FFNd = 8960;
constexpr int Bb   = 2;
constexpr int Ss   = 2048;
constexpr int Le   = 512;
constexpr int NTOK = Bb * Ss;          // 4096
constexpr int NENC = Bb * Le;          // 1024
}

// ---- fp32 scratch ---------------------------------------------------------
__device__ float g_q[NTOK * Dm];
__device__ float g_k[NTOK * Dm];
__device__ float g_v[NTOK * Dm];
__device__ float g_t[NTOK * Dm];
__device__ float g_h[NTOK * Dm];
__device__ float g_s[Bb * Hn * Ss * Ss];

// ---- bf16 hi/lo activation scratch ---------------------------------------
__device__ __nv_bfloat16 g_xhi[NTOK * Dm], g_xlo[NTOK * Dm];
__device__ __nv_bfloat16 g_hhi[NTOK * Dm], g_hlo[NTOK * Dm];
__device__ __nv_bfloat16 g_ehi[NENC * Dm], g_elo[NENC * Dm];
__device__ __nv_bfloat16 g_fhi[NTOK * FFNd], g_flo[NTOK * FFNd];
__device__ __nv_bfloat16 g_qhi[NTOK * Dm], g_qlo[NTOK * Dm];
__device__ __nv_bfloat16 g_khi[NTOK * Dm], g_klo[NTOK * Dm];
__device__ __nv_bfloat16 g_vthi[NTOK * Dm], g_vtlo[NTOK * Dm];
__device__ __nv_bfloat16 g_phi[Bb * Hn * Ss * Ss], g_plo[Bb * Hn * Ss * Ss];

// ---- bf16 hi/lo transposed weights ([N][K] row-major, K contiguous) -------
__device__ __nv_bfloat16 g_wsq_hi[8 * Dm * Dm], g_wsq_lo[8 * Dm * Dm];
__device__ __nv_bfloat16 g_wf1_hi[FFNd * Dm],  g_wf1_lo[FFNd * Dm];
__device__ __nv_bfloat16 g_wf2_hi[Dm * FFNd],  g_wf2_lo[Dm * FFNd];

__device__ __forceinline__ void* dev_buf(int id) {
    switch (id) {
        case 0:  return (void*)g_q;
        case 1:  return (void*)g_k;
        case 2:  return (void*)g_v;
        case 4:  return (void*)g_t;
        case 5:  return (void*)g_h;
        case 6:  return (void*)g_s;
        case 7:  return (void*)g_xhi;
        case 8:  return (void*)g_xlo;
        case 9:  return (void*)g_hhi;
        case 10: return (void*)g_hlo;
        case 11: return (void*)g_ehi;
        case 12: return (void*)g_elo;
        case 13: return (void*)g_fhi;
        case 14: return (void*)g_flo;
        case 15: return (void*)g_wsq_hi;
        case 16: return (void*)g_wsq_lo;
        case 17: return (void*)g_wf1_hi;
        case 18: return (void*)g_wf1_lo;
        case 19: return (void*)g_wf2_hi;
        case 20: return (void*)g_wf2_lo;
        case 21: return (void*)g_qhi;
        case 22: return (void*)g_qlo;
        case 23: return (void*)g_khi;
        case 24: return (void*)g_klo;
        case 25: return (void*)g_vthi;
        case 26: return (void*)g_vtlo;
        case 27: return (void*)g_phi;
        case 28: return (void*)g_plo;
    }
    return nullptr;
}

__device__ __forceinline__ uint32_t smem_to_u32(const void* p) {
    uint32_t a;
    asm("{ .reg .u64 t; cvta.to.shared.u64 t, %1; cvt.u32.u64 %0, t; }"
        : "=r"(a) : "l"(p));
    return a;
}

// ---- mma.sync / ldmatrix / cp.async helpers (sm_80+) ----------------------
__device__ __forceinline__ void ldsm_x4(uint32_t* r, uint32_t addr) {
    asm volatile("ldmatrix.sync.aligned.m8n8.x4.shared.b16 {%0,%1,%2,%3}, [%4];"
        : "=r"(r[0]), "=r"(r[1]), "=r"(r[2]), "=r"(r[3]) : "r"(addr));
}
__device__ __forceinline__ void mma_bf16(float* c, const uint32_t* a, const uint32_t* b) {
    asm volatile(
        "mma.sync.aligned.m16n8k16.row.col.f32.bf16.bf16.f32 "
        "{%0,%1,%2,%3}, {%4,%5,%6,%7}, {%8,%9}, {%0,%1,%2,%3};"
        : "+f"(c[0]), "+f"(c[1]), "+f"(c[2]), "+f"(c[3])
        : "r"(a[0]), "r"(a[1]), "r"(a[2]), "r"(a[3]), "r"(b[0]), "r"(b[1]));
}
__device__ __forceinline__ void cp16(uint32_t s, const void* g) {
    asm volatile("cp.async.cg.shared.global [%0], [%1], 16;" :: "r"(s), "l"(g));
}
#define CP_COMMIT() asm volatile("cp.async.commit_group;" ::: "memory")
#define CP_WAIT0()  asm volatile("cp.async.wait_group 0;"  ::: "memory")

__device__ __forceinline__ float gelu_fast(float x) {
    float z = 1.5957691216057308f * (x + 0.044715f * x * x * x);
    return x / (1.0f + __expf(-z));
}

// ===========================================================================
// bf16 3-pass GEMM: C[M,N] = A[M,K] * B[N,K]^T  (+scale, +bias, +gelu)
// Block 128x128, 8 warps (2x4), warp tile 64x32, K-chunk 16, 2-stage cp.async,
// static 48KB smem, 2 CTAs/SM (16 warps).
// ===========================================================================
namespace {
constexpr int KC  = 16;
constexpr int RS  = 24;                 // row stride (elems); 48B conflict-free
constexpr int TSE = 128 * RS;           // 3072 elems per tile
}

__global__ __launch_bounds__(256, 2) void gemm_mma_k(
    int ahiId, int aloId, int lda, long long aOffB, long long aOffH,
    int bhiId, int bloId, int ldb, long long bOff0, long long bOffB, long long bOffH,
    float* cfExt, int cfId, int chiId, int cloId, int ldc, long long cOffB, long long cOffH,
    const float* __restrict__ bias, int K, int act, float cscale)
{
    __shared__ __align__(16) __nv_bfloat16 smem[2 * 4 * TSE];   // 49152 B

    const int z = blockIdx.z;
    const int bz = z / Hn;
    const int hz = z - bz * Hn;

    const __nv_bfloat16* Ahi = (const __nv_bfloat16*)dev_buf(ahiId) + bz * aOffB + hz * aOffH;
    const __nv_bfloat16* Alo = (const __nv_bfloat16*)dev_buf(aloId) + bz * aOffB + hz * aOffH;
    const __nv_bfloat16* Bhi = (const __nv_bfloat16*)dev_buf(bhiId) + bOff0 + bz * bOffB + hz * bOffH;
    const __nv_bfloat16* Blo = (const __nv_bfloat16*)dev_buf(bloId) + bOff0 + bz * bOffB + hz * bOffH;
    long long cOff = bz * cOffB + hz * cOffH;
    float* Cf = cfExt ? cfExt : (cfId >= 0 ? (float*)dev_buf(cfId) : nullptr);
    if (Cf) Cf += cOff;
    __nv_bfloat16* Chi = (chiId >= 0) ? (__nv_bfloat16*)dev_buf(chiId) + cOff : nullptr;
    __nv_bfloat16* Clo = (cloId >= 0) ? (__nv_bfloat16*)dev_buf(cloId) + cOff : nullptr;

    const int tid  = threadIdx.x;
    const int wid  = tid >> 5;
    const int lane = tid & 31;
    const int wm   = (wid & 1) * 64;
    const int wn   = (wid >> 1) * 32;
    const int row0 = blockIdx.y * 128;
    const int col0 = blockIdx.x * 128;

    const uint32_t sbase = smem_to_u32(smem);
    const int lm = tid >> 1;
    const int lc = (tid & 1) * 8;

    const int a_r = lane & 15;
    const int a_c = (lane >> 4) * 8;
    // B x4 pair-load lane coords: matrix = lane>>3 selects (j-offset, k-half)
    const int bp_row = (lane >> 4) * 8 + (lane & 7);   // j-offset*8 + row
    const int bp_col = ((lane >> 3) & 1) * 8;          // k-half

    float acc[4][4][4];
#pragma unroll
    for (int i = 0; i < 4; i++)
#pragma unroll
        for (int j = 0; j < 4; j++)
#pragma unroll
            for (int r = 0; r < 4; r++) acc[i][j][r] = 0.0f;

    const int NC = K / KC;

    auto load_chunk = [&](int stg, int k0) {
        uint32_t sb = sbase + (uint32_t)(stg * 4 * TSE) * 2;
        uint32_t so = (uint32_t)(lm * RS + lc) * 2;
        size_t ga = (size_t)(row0 + lm) * lda + k0 + lc;
        size_t gb = (size_t)(col0 + lm) * ldb + k0 + lc;
        cp16(sb + so,                          Ahi + ga);
        cp16(sb + (uint32_t)TSE * 2     + so,  Alo + ga);
        cp16(sb + (uint32_t)TSE * 2 * 2 + so,  Bhi + gb);
        cp16(sb + (uint32_t)TSE * 2 * 3 + so,  Blo + gb);
        CP_COMMIT();
    };

    load_chunk(0, 0);

    for (int c = 0; c < NC; c++) {
        CP_WAIT0();
        __syncthreads();
        if (c + 1 < NC) load_chunk((c + 1) & 1, (c + 1) * KC);

        const uint32_t sb = sbase + (uint32_t)((c & 1) * 4 * TSE) * 2;
        const uint32_t aHiB = sb;
        const uint32_t aLoB = sb + (uint32_t)TSE * 2;
        const uint32_t bHiB = sb + (uint32_t)TSE * 2 * 2;
        const uint32_t bLoB = sb + (uint32_t)TSE * 2 * 3;

        uint32_t bh[4][2], bl[4][2];
#pragma unroll
        for (int jp = 0; jp < 2; jp++) {
            int j = jp * 2;
            uint32_t ad = (uint32_t)(((wn + j * 8 + bp_row) * RS + bp_col) * 2);
            uint32_t r[4];
            ldsm_x4(r, bHiB + ad);
            bh[j][0] = r[0]; bh[j][1] = r[1];
            bh[j + 1][0] = r[2]; bh[j + 1][1] = r[3];
            ldsm_x4(r, bLoB + ad);
            bl[j][0] = r[0]; bl[j][1] = r[1];
            bl[j + 1][0] = r[2]; bl[j + 1][1] = r[3];
        }
#pragma unroll
        for (int i = 0; i < 4; i++) {
            uint32_t ad = (uint32_t)(((wm + i * 16 + a_r) * RS + a_c) * 2);
            uint32_t ah[4], al[4];
            ldsm_x4(ah, aHiB + ad);
            ldsm_x4(al, aLoB + ad);
#pragma unroll
            for (int j = 0; j < 4; j++) {
                mma_bf16(acc[i][j], ah, bh[j]);
                mma_bf16(acc[i][j], ah, bl[j]);
                mma_bf16(acc[i][j], al, bh[j]);
            }
        }
        __syncthreads();
    }

    // ---- epilogue ----
    const int er = lane >> 2;
    const int ec = (lane & 3) * 2;
#pragma unroll
    for (int i = 0; i < 4; i++) {
#pragma unroll
        for (int rr = 0; rr < 2; rr++) {
            size_t m = (size_t)(row0 + wm + i * 16 + er + rr * 8);
#pragma unroll
            for (int j = 0; j < 4; j++) {
                int n = col0 + wn + j * 8 + ec;
                float v0 = acc[i][j][rr * 2 + 0] * cscale;
                float v1 = acc[i][j][rr * 2 + 1] * cscale;
                if (bias) { v0 += bias[n]; v1 += bias[n + 1]; }
                if (act == 1) { v0 = gelu_fast(v0); v1 = gelu_fast(v1); }
                if (Cf) {
                    float2 o; o.x = v0; o.y = v1;
                    *(float2*)&Cf[m * (size_t)ldc + n] = o;
                }
                if (Chi) {
                    __nv_bfloat16 h0 = __float2bfloat16(v0);
                    __nv_bfloat16 h1 = __float2bfloat16(v1);
                    __nv_bfloat16 l0 = __float2bfloat16(v0 - __bfloat162float(h0));
                    __nv_bfloat16 l1 = __float2bfloat16(v1 - __bfloat162float(h1));
                    __nv_bfloat162 ph; ph.x = h0; ph.y = h1;
                    __nv_bfloat162 pl; pl.x = l0; pl.y = l1;
                    *(__nv_bfloat162*)&Chi[m * (size_t)ldc + n] = ph;
                    *(__nv_bfloat162*)&Clo[m * (size_t)ldc + n] = pl;
                }
            }
        }
    }
}

// ===========================================================================
// Weight transpose + hi/lo conversion: W[K,N] -> T[N,K]
// ===========================================================================
__global__ __launch_bounds__(256) void transp_conv_k(
    const float* __restrict__ W, int thiId, int tloId, long long off, int K, int N)
{
    __nv_bfloat16* Thi = (__nv_bfloat16*)dev_buf(thiId) + off;
    __nv_bfloat16* Tlo = (__nv_bfloat16*)dev_buf(tloId) + off;
    __shared__ float tile[32][33];
    int nx = blockIdx.x * 32, ky = blockIdx.y * 32;
    int tx = threadIdx.x, ty = threadIdx.y;
#pragma unroll
    for (int j = 0; j < 32; j += 8)
        tile[ty + j][tx] = W[(size_t)(ky + ty + j) * N + nx + tx];
    __syncthreads();
#pragma unroll
    for (int j = 0; j < 32; j += 8) {
        float v = tile[tx][ty + j];
        size_t o = (size_t)(nx + ty + j) * K + ky + tx;
        __nv_bfloat16 hi = __float2bfloat16(v);
        Thi[o] = hi;
        Tlo[o] = __float2bfloat16(v - __bfloat162float(hi));
    }
}

// fp32 -> bf16 hi/lo
__global__ __launch_bounds__(256) void conv_k(
    const float* srcExt, int srcId, int hiId, int loId, int n)
{
    const float* src = srcExt ? srcExt : (const float*)dev_buf(srcId);
    __nv_bfloat16* hi = (__nv_bfloat16*)dev_buf(hiId);
    __nv_bfloat16* lo = (__nv_bfloat16*)dev_buf(loId);
    int i = blockIdx.x * 256 + threadIdx.x;
    if (i >= n) return;
    float v = src[i];
    __nv_bfloat16 h = __float2bfloat16(v);
    hi[i] = h;
    lo[i] = __float2bfloat16(v - __bfloat162float(h));
}

// ===========================================================================
// LayerNorm + AdaLN modulation -> bf16 hi/lo
// ===========================================================================
__global__ __launch_bounds__(256) void ln_mod_k(
    int dhiId, int dloId, const float* srcExt, int srcId,
    const float* __restrict__ temb, const float* __restrict__ sst,
    const int* __restrict__ segp, int jshift, int jscale)
{
    __nv_bfloat16* dhi = (__nv_bfloat16*)dev_buf(dhiId);
    __nv_bfloat16* dlo = (__nv_bfloat16*)dev_buf(dloId);
    const float* src = srcExt ? srcExt : (const float*)dev_buf(srcId);
    int tok = blockIdx.x;
    int b = tok / Ss;
    int s = tok - b * Ss;
    int si = segp[0];
    si = si < 0 ? 0 : (si > Ss ? Ss : si);
    int seg = (s >= si) ? 1 : 0;

    const float* x = src + (size_t)tok * Dm;
    int tid = threadIdx.x;
    float lsum = 0.0f, lsq = 0.0f;
    for (int d = tid; d < Dm; d += 256) {
        float v = x[d];
        lsum += v; lsq += v * v;
    }
    __shared__ float r1[256], r2[256];
    r1[tid] = lsum; r2[tid] = lsq;
    __syncthreads();
    for (int o = 128; o > 0; o >>= 1) {
        if (tid < o) { r1[tid] += r1[tid + o]; r2[tid] += r2[tid + o]; }
        __syncthreads();
    }
    float mu = r1[0] * (1.0f / Dm);
    float var = r2[0] * (1.0f / Dm) - mu * mu;
    float rstd = rsqrtf(var + 1e-6f);

    const float* tb_sc = temb + ((size_t)(b * 6 + jscale) * 2 + seg) * Dm;
    const float* tb_sh = temb + ((size_t)(b * 6 + jshift) * 2 + seg) * Dm;
    size_t base = (size_t)tok * Dm;
    for (int d = tid; d < Dm; d += 256) {
        float sc = sst[jscale * Dm + d] + tb_sc[d];
        float sh = sst[jshift * Dm + d] + tb_sh[d];
        float v = (x[d] - mu) * rstd * (1.0f + sc) + sh;
        __nv_bfloat16 h = __float2bfloat16(v);
        dhi[base + d] = h;
        dlo[base + d] = __float2bfloat16(v - __bfloat162float(h));
    }
}

// ===========================================================================
// RoPE: read g_q/g_k fp32, rotate, emit hi/lo bf16
// ===========================================================================
__global__ __launch_bounds__(256) void rope_split_k(const float* cs, const float* sn)
{
    int idx = blockIdx.x * 256 + threadIdx.x;
    const int total = NTOK * Hn * (DHd / 2);
    if (idx >= total) return;
    int i = idx & 63;
    int h = (idx >> 6) % Hn;
    int tok = idx / (64 * Hn);
    float c = cs[(size_t)tok * 64 + i];
    float sv = sn[(size_t)tok * 64 + i];
    size_t base = (size_t)tok * Dm + h * DHd + 2 * i;

    float xr = g_q[base], xi = g_q[base + 1];
    float o0 = xr * c - xi * sv;
    float o1 = xr * sv + xi * c;
    __nv_bfloat16 h0 = __float2bfloat16(o0);
    __nv_bfloat16 h1 = __float2bfloat16(o1);
    g_qhi[base] = h0; g_qhi[base + 1] = h1;
    g_qlo[base]     = __float2bfloat16(o0 - __bfloat162float(h0));
    g_qlo[base + 1] = __float2bfloat16(o1 - __bfloat162float(h1));

    xr = g_k[base]; xi = g_k[base + 1];
    o0 = xr * c - xi * sv;
    o1 = xr * sv + xi * c;
    h0 = __float2bfloat16(o0);
    h1 = __float2bfloat16(o1);
    g_khi[base] = h0; g_khi[base + 1] = h1;
    g_klo[base]     = __float2bfloat16(o0 - __bfloat162float(h0));
    g_klo[base + 1] = __float2bfloat16(o1 - __bfloat162float(h1));
}

// ===========================================================================
// V transpose per head: g_v [b*Lkv+n][h*128+d] -> vt[z][d][n] (hi/lo bf16)
// ===========================================================================
__global__ void vt_k(int Lkv)
{
    __shared__ float t[32][33];
    int z = blockIdx.z, b = z / Hn, h = z - b * Hn;
    int n0 = blockIdx.x * 32, d0 = blockIdx.y * 32;
    int tx = threadIdx.x, ty = threadIdx.y;
#pragma unroll
    for (int j = 0; j < 32; j += 8)
        t[ty + j][tx] = g_v[(size_t)(b * Lkv + n0 + ty + j) * Dm + h * DHd + d0 + tx];
    __syncthreads();
    size_t zb = (size_t)z * DHd * Lkv;
#pragma unroll
    for (int j = 0; j < 32; j += 8) {
        float v = t[tx][ty + j];
        size_t o = zb + (size_t)(d0 + ty + j) * Lkv + n0 + tx;
        __nv_bfloat16 hi = __float2bfloat16(v);
        g_vthi[o] = hi;
        g_vtlo[o] = __float2bfloat16(v - __bfloat162float(hi));
    }
}

// ===========================================================================
// Register-resident softmax -> P bf16 hi/lo. One 256-thread block per row.
// ===========================================================================
__global__ __launch_bounds__(256) void softmax_bf_k(int Lkv)
{
    long long base = (long long)blockIdx.x * Lkv;
    const float* p = g_s + base;
    int tid = threadIdx.x;
    int ne = Lkv >> 8;              // 8 (self) or 2 (cross)
    float vals[8];
    __shared__ float red[256];

    float m = -1e30f;
    for (int e = 0; e < ne; e++) {
        vals[e] = p[e * 256 + tid];
        m = fmaxf(m, vals[e]);
    }
    red[tid] = m;
    __syncthreads();
    for (int o = 128; o > 0; o >>= 1) {
        if (tid < o) red[tid] = fmaxf(red[tid], red[tid + o]);
        __syncthreads();
    }
    float mx = red[0];
    __syncthreads();

    float s = 0.0f;
    for (int e = 0; e < ne; e++) {
        float ev = __expf(vals[e] - mx);
        vals[e] = ev;
        s += ev;
    }
    red[tid] = s;
    __syncthreads();
    for (int o = 128; o > 0; o >>= 1) {
        if (tid < o) red[tid] += red[tid + o];
        __syncthreads();
    }
    float inv = 1.0f / red[0];
    for (int e = 0; e < ne; e++) {
        float ev = vals[e] * inv;
        __nv_bfloat16 h = __float2bfloat16(ev);
        g_phi[base + e * 256 + tid] = h;
        g_plo[base + e * 256 + tid] = __float2bfloat16(ev - __bfloat162float(h));
    }
}

// ===========================================================================
// Gated residual: dst = hsrc + g_t*mod[j]; optional bf16 hi/lo duplicate
// ===========================================================================
__global__ __launch_bounds__(256) void resid_gate_k(
    float* dstExt, int dstId, int dhiId, int dloId,
    const float* hExt, int hId,
    const float* __restrict__ temb, const float* __restrict__ sst,
    const int* __restrict__ segp, int j)
{
    float* dst = dstExt ? dstExt : (float*)dev_buf(dstId);
    const float* h = hExt ? hExt : (const float*)dev_buf(hId);
    __nv_bfloat16* dhi = (dhiId >= 0) ? (__nv_bfloat16*)dev_buf(dhiId) : nullptr;
    __nv_bfloat16* dlo = (dloId >= 0) ? (__nv_bfloat16*)dev_buf(dloId) : nullptr;
    int idx = blockIdx.x * 256 + threadIdx.x;
    int d = idx % Dm;
    int tok = idx / Dm;
    int b = tok / Ss;
    int s = tok - b * Ss;
    int si = segp[0];
    si = si < 0 ? 0 : (si > Ss ? Ss : si);
    int seg = (s >= si) ? 1 : 0;
    float g = sst[j * Dm + d] + temb[((size_t)(b * 6 + j) * 2 + seg) * Dm + d];
    float v = h[idx] + g_t[idx] * g;
    dst[idx] = v;
    if (dhi) {
        __nv_bfloat16 hh = __float2bfloat16(v);
        dhi[idx] = hh;
        dlo[idx] = __float2bfloat16(v - __bfloat162float(hh));
    }
}

__global__ __launch_bounds__(256) void resid_add_k()
{
    int idx = blockIdx.x * 256 + threadIdx.x;
    g_h[idx] += g_t[idx];
}

// ===========================================================================
extern "C" void kernel_launch(void* const* d_in, const int* in_sizes, int n_in,
                              void* d_out, int out_size)
{
    const float* hidden = (const float*)d_in[0];
    const float* enc    = (const float*)d_in[1];
    const float* temb   = (const float*)d_in[2];
    const float* rc     = (const float*)d_in[3];
    const float* rs     = (const float*)d_in[4];
    const int*   seg    = (const int*)d_in[5];
    const float* Wq1 = (const float*)d_in[6];
    const float* Wk1 = (const float*)d_in[7];
    const float* Wv1 = (const float*)d_in[8];
    const float* Wo1 = (const float*)d_in[9];
    const float* bo1 = (const float*)d_in[10];
    const float* Wq2 = (const float*)d_in[11];
    const float* Wk2 = (const float*)d_in[12];
    const float* Wv2 = (const float*)d_in[13];
    const float* Wo2 = (const float*)d_in[14];
    const float* bo2 = (const float*)d_in[15];
    const float* Wf1 = (const float*)d_in[16];
    const float* bf1 = (const float*)d_in[17];
    const float* Wf2 = (const float*)d_in[18];
    const float* bf2 = (const float*)d_in[19];
    const float* sst = (const float*)d_in[20];
    float* out = (float*)d_out;

    const float scale = 0.08838834764831845f;  // 1/sqrt(128)
    const long long DD = (long long)Dm * Dm;
    const int nElem = NTOK * Dm;

    // ---- 0. weight transposes + hi/lo conversions --------------------------
    {
        dim3 tb(32, 8);
        dim3 gs(Dm / 32, Dm / 32);
        transp_conv_k<<<gs, tb>>>(Wq1, 15, 16, 0 * DD, Dm, Dm);
        transp_conv_k<<<gs, tb>>>(Wk1, 15, 16, 1 * DD, Dm, Dm);
        transp_conv_k<<<gs, tb>>>(Wv1, 15, 16, 2 * DD, Dm, Dm);
        transp_conv_k<<<gs, tb>>>(Wo1, 15, 16, 3 * DD, Dm, Dm);
        transp_conv_k<<<gs, tb>>>(Wq2, 15, 16, 4 * DD, Dm, Dm);
        transp_conv_k<<<gs, tb>>>(Wk2, 15, 16, 5 * DD, Dm, Dm);
        transp_conv_k<<<gs, tb>>>(Wv2, 15, 16, 6 * DD, Dm, Dm);
        transp_conv_k<<<gs, tb>>>(Wo2, 15, 16, 7 * DD, Dm, Dm);
        transp_conv_k<<<dim3(FFNd / 32, Dm / 32), tb>>>(Wf1, 17, 18, 0, Dm, FFNd);
        transp_conv_k<<<dim3(Dm / 32, FFNd / 32), tb>>>(Wf2, 19, 20, 0, FFNd, Dm);
    }

    dim3 gproj(Dm / 128, NTOK / 128);   // (12, 32)

    // ---- 1. LN + modulation -> x(hi/lo) ------------------------------------
    ln_mod_k<<<NTOK, 256>>>(7, 8, hidden, -1, temb, sst, seg, 0, 1);

    // ---- 2. QKV projections --------------------------------------------------
    gemm_mma_k<<<gproj, 256>>>(7, 8, Dm, 0, 0, 15, 16, Dm, 0 * DD, 0, 0,
                               nullptr, 0, -1, -1, Dm, 0, 0, nullptr, Dm, 0, 1.0f);
    gemm_mma_k<<<gproj, 256>>>(7, 8, Dm, 0, 0, 15, 16, Dm, 1 * DD, 0, 0,
                               nullptr, 1, -1, -1, Dm, 0, 0, nullptr, Dm, 0, 1.0f);
    gemm_mma_k<<<gproj, 256>>>(7, 8, Dm, 0, 0, 15, 16, Dm, 2 * DD, 0, 0,
                               nullptr, 2, -1, -1, Dm, 0, 0, nullptr, Dm, 0, 1.0f);

    // ---- 3. RoPE -> q/k hi/lo; V transpose -> vt hi/lo ---------------------
    rope_split_k<<<(NTOK * Hn * 64) / 256, 256>>>(rc, rs);
    vt_k<<<dim3(Ss / 32, DHd / 32, Bb * Hn), dim3(32, 8)>>>(Ss);

    // ---- 4. self QK^T (scaled) -> g_s --------------------------------------
    gemm_mma_k<<<dim3(Ss / 128, Ss / 128, Bb * Hn), 256>>>(
        21, 22, Dm, (long long)Ss * Dm, DHd,
        23, 24, Dm, 0, (long long)Ss * Dm, DHd,
        nullptr, 6, -1, -1, Ss, (long long)Hn * Ss * Ss, (long long)Ss * Ss,
        nullptr, DHd, 0, scale);

    // ---- 5. softmax -> P hi/lo ---------------------------------------------
    softmax_bf_k<<<Bb * Hn * Ss, 256>>>(Ss);

    // ---- 6. PV -> attention out hi/lo (merged layout) ----------------------
    gemm_mma_k<<<dim3(1, Ss / 128, Bb * Hn), 256>>>(
        27, 28, Ss, (long long)Hn * Ss * Ss, (long long)Ss * Ss,
        25, 26, Ss, 0, (long long)Hn * DHd * Ss, (long long)DHd * Ss,
        nullptr, -1, 7, 8, Dm, (long long)Ss * Dm, DHd,
        nullptr, Ss, 0, 1.0f);

    // ---- 7. out projection 1 (+bias) -> g_t --------------------------------
    gemm_mma_k<<<gproj, 256>>>(7, 8, Dm, 0, 0, 15, 16, Dm, 3 * DD, 0, 0,
                               nullptr, 4, -1, -1, Dm, 0, 0, bo1, Dm, 0, 1.0f);

    // ---- 8. gated residual -> g_h (+hi/lo) ---------------------------------
    resid_gate_k<<<nElem / 256, 256>>>(nullptr, 5, 9, 10, hidden, -1,
                                       temb, sst, seg, 2);

    // ---- 9. cross projections ----------------------------------------------
    gemm_mma_k<<<gproj, 256>>>(9, 10, Dm, 0, 0, 15, 16, Dm, 4 * DD, 0, 0,
                               nullptr, -1, 21, 22, Dm, 0, 0, nullptr, Dm, 0, 1.0f);
    conv_k<<<(NENC * Dm) / 256, 256>>>(enc, -1, 11, 12, NENC * Dm);
    dim3 gkv(Dm / 128, NENC / 128);   // (12, 8)
    gemm_mma_k<<<gkv, 256>>>(11, 12, Dm, 0, 0, 15, 16, Dm, 5 * DD, 0, 0,
                             nullptr, -1, 23, 24, Dm, 0, 0, nullptr, Dm, 0, 1.0f);
    gemm_mma_k<<<gkv, 256>>>(11, 12, Dm, 0, 0, 15, 16, Dm, 6 * DD, 0, 0,
                             nullptr, 2, -1, -1, Dm, 0, 0, nullptr, Dm, 0, 1.0f);
    vt_k<<<dim3(Le / 32, DHd / 32, Bb * Hn), dim3(32, 8)>>>(Le);

    // ---- 10. cross attention ------------------------------------------------
    gemm_mma_k<<<dim3(Le / 128, Ss / 128, Bb * Hn), 256>>>(
        21, 22, Dm, (long long)Ss * Dm, DHd,
        23, 24, Dm, 0, (long long)Le * Dm, DHd,
        nullptr, 6, -1, -1, Le, (long long)Hn * Ss * Le, (long long)Ss * Le,
        nullptr, DHd, 0, scale);
    softmax_bf_k<<<Bb * Hn * Ss, 256>>>(Le);
    gemm_mma_k<<<dim3(1, Ss / 128, Bb * Hn), 256>>>(
        27, 28, Le, (long long)Hn * Ss * Le, (long long)Ss * Le,
        25, 26, Le, 0, (long long)Hn * DHd * Le, (long long)DHd * Le,
        nullptr, -1, 7, 8, Dm, (long long)Ss * Dm, DHd,
        nullptr, Le, 0, 1.0f);

    // ---- 11. out projection 2 (+bias) + residual ---------------------------
    gemm_mma_k<<<gproj, 256>>>(7, 8, Dm, 0, 0, 15, 16, Dm, 7 * DD, 0, 0,
                               nullptr, 4, -1, -1, Dm, 0, 0, bo2, Dm, 0, 1.0f);
    resid_add_k<<<nElem / 256, 256>>>();

    // ---- 12. LN + c_shift/c_scale -> x(hi/lo) ------------------------------
    ln_mod_k<<<NTOK, 256>>>(7, 8, nullptr, 5, temb, sst, seg, 3, 4);

    // ---- 13. FFN up (+bias +gelu) -> f(hi/lo) ------------------------------
    gemm_mma_k<<<dim3(FFNd / 128, NTOK / 128), 256>>>(
        7, 8, Dm, 0, 0, 17, 18, Dm, 0, 0, 0,
        nullptr, -1, 13, 14, FFNd, 0, 0, bf1, Dm, 1, 1.0f);

    // ---- 14. FFN down (+bias) ----------------------------------------------
    gemm_mma_k<<<gproj, 256>>>(13, 14, FFNd, 0, 0, 19, 20, FFNd, 0, 0, 0,
                               nullptr, 4, -1, -1, Dm, 0, 0, bf2, FFNd, 0, 1.0f);

    // ---- 15. final gated residual -> d_out ---------------------------------
    resid_gate_k<<<nElem / 256, 256>>>(out, -1, -1, -1, nullptr, 5,
                                       temb, sst, seg, 5);
}